// round 14
// baseline (speedup 1.0000x reference)
#include <cuda_runtime.h>
#include <cuda_bf16.h>
#include <cstdint>
#include <math.h>

// Problem dims
#define T_DIM 4096
#define H_DIM 4096
#define I_DIM 11008

// ---------------- device scratch (static globals: allocation-free) ----------
__device__ __nv_bfloat16 g_x_bf[(size_t)T_DIM * H_DIM];        // 33.6 MB
__device__ __nv_bfloat16 g_wgu_bf[(size_t)2 * I_DIM * H_DIM];  // 180.4 MB
__device__ __nv_bfloat16 g_wd_bf[(size_t)H_DIM * I_DIM];       // 90.2 MB
__device__ float         g_y[(size_t)T_DIM * I_DIM];           // 180.4 MB
__device__ __nv_bfloat16 g_yq_bf[(size_t)T_DIM * I_DIM];       // 90.2 MB
__device__ unsigned      g_rowmax[T_DIM];

// ---------------- helpers ----------------------------------------------------
__device__ __forceinline__ uint32_t smem_u32(const void* p) {
    uint32_t a;
    asm("{ .reg .u64 t; cvta.to.shared.u64 t, %1; cvt.u32.u64 %0, t; }" : "=r"(a) : "l"(p));
    return a;
}

__device__ __forceinline__ uint32_t sw128(uint32_t off) {
    return off ^ ((off >> 3) & 0x70);
}

__device__ __forceinline__ void cp_async16(uint32_t dst, const void* src) {
    asm volatile("cp.async.cg.shared.global [%0], [%1], 16;" :: "r"(dst), "l"(src));
}
#define CP_COMMIT() asm volatile("cp.async.commit_group;" ::: "memory")
#define CP_WAIT1()  asm volatile("cp.async.wait_group 1;" ::: "memory")

__device__ __forceinline__ void ldsm_x4(uint32_t addr, uint32_t& r0, uint32_t& r1,
                                        uint32_t& r2, uint32_t& r3) {
    asm volatile("ldmatrix.sync.aligned.m8n8.x4.shared.b16 {%0,%1,%2,%3}, [%4];"
                 : "=r"(r0), "=r"(r1), "=r"(r2), "=r"(r3) : "r"(addr));
}

// bf16 HMMA: D(f32) += A(bf16) * B(bf16)
__device__ __forceinline__ void mma_bf16(float* c, const uint32_t* a, uint32_t b0, uint32_t b1) {
    asm volatile(
        "mma.sync.aligned.m16n8k16.row.col.f32.bf16.bf16.f32 "
        "{%0,%1,%2,%3}, {%4,%5,%6,%7}, {%8,%9}, {%0,%1,%2,%3};"
        : "+f"(c[0]), "+f"(c[1]), "+f"(c[2]), "+f"(c[3])
        : "r"(a[0]), "r"(a[1]), "r"(a[2]), "r"(a[3]), "r"(b0), "r"(b1));
}

// ldmatrix lane address inside a [rows x 128B] SW128 tile. kcb = k offset in BYTES.
__device__ __forceinline__ uint32_t lds_addr(uint32_t tile_base, int lane, int mb, int kcb) {
    int row = mb + (lane & 7) + ((lane >> 3) & 1) * 8;
    int kb  = kcb + ((lane >> 4) & 1) * 16;
    return tile_base + sw128((uint32_t)(row * 128 + kb));
}

// ---------------- fused init: converts + rowmax zero --------------------------
__device__ __forceinline__ void conv_seg(const int* __restrict__ src,
                                         __nv_bfloat16* __restrict__ dst,
                                         int n4, int idx, int stride) {
    const int4* s4 = (const int4*)src;
    ushort4* d4 = (ushort4*)dst;
    for (int i = idx; i < n4; i += stride) {
        int4 v = s4[i];
        ushort4 o;
        o.x = __bfloat16_as_ushort(__float2bfloat16_rn((float)v.x));
        o.y = __bfloat16_as_ushort(__float2bfloat16_rn((float)v.y));
        o.z = __bfloat16_as_ushort(__float2bfloat16_rn((float)v.z));
        o.w = __bfloat16_as_ushort(__float2bfloat16_rn((float)v.w));
        d4[i] = o;
    }
}

__global__ __launch_bounds__(256) void init_kernel(const int* __restrict__ x_q,
                                                   const int* __restrict__ w_gu,
                                                   const int* __restrict__ w_d) {
    int idx = blockIdx.x * blockDim.x + threadIdx.x;
    int stride = gridDim.x * blockDim.x;
    conv_seg(x_q,  g_x_bf,   (int)((size_t)T_DIM * H_DIM / 4),     idx, stride);
    conv_seg(w_gu, g_wgu_bf, (int)((size_t)2 * I_DIM * H_DIM / 4), idx, stride);
    conv_seg(w_d,  g_wd_bf,  (int)((size_t)H_DIM * I_DIM / 4),     idx, stride);
    for (int i = idx; i < T_DIM; i += stride) g_rowmax[i] = 0u;
}

__global__ __launch_bounds__(256) void quantize_kernel() {
    int t = blockIdx.x;
    float s2 = fmaxf(__uint_as_float(g_rowmax[t]), 1e-8f) / 127.0f;
    float inv = __frcp_rn(s2);
    const float4* y4 = (const float4*)(g_y + (size_t)t * I_DIM);
    ushort4* q4 = (ushort4*)(g_yq_bf + (size_t)t * I_DIM);
    for (int i = threadIdx.x; i < I_DIM / 4; i += 256) {
        float4 v = y4[i];
        ushort4 o;
        o.x = __bfloat16_as_ushort(__float2bfloat16_rn(fminf(fmaxf(rintf(v.x * inv), -128.f), 127.f)));
        o.y = __bfloat16_as_ushort(__float2bfloat16_rn(fminf(fmaxf(rintf(v.y * inv), -128.f), 127.f)));
        o.z = __bfloat16_as_ushort(__float2bfloat16_rn(fminf(fmaxf(rintf(v.z * inv), -128.f), 127.f)));
        o.w = __bfloat16_as_ushort(__float2bfloat16_rn(fminf(fmaxf(rintf(v.w * inv), -128.f), 127.f)));
        q4[i] = o;
    }
}

// =====================  GEMM1: x @ wgu^T, fused SiLU*up  =====================
// CTA: 128 rows x (64 gate + 64 up cols). 3 buffers, loads 2 stages ahead,
// ONE sync per iteration.
#define G1_STAGE 32768
#define G1_SMEM  (3 * G1_STAGE)

__device__ __forceinline__ void g1_load(uint32_t stage, int tid, int m0, int n0, int kk) {
    const int k0 = kk << 6;
#pragma unroll
    for (int i = 0; i < 4; i++) {  // A: 128 rows
        int c = tid + (i << 8);
        int row = c >> 3, c16 = c & 7;
        cp_async16(stage + sw128((uint32_t)((row << 7) | (c16 << 4))),
                   &g_x_bf[(size_t)(m0 + row) * H_DIM + k0 + c16 * 8]);
    }
#pragma unroll
    for (int i = 0; i < 2; i++) {  // Bg + Bu: 64 rows each
        int c = tid + (i << 8);
        int row = c >> 3, c16 = c & 7;
        uint32_t sw = sw128((uint32_t)((row << 7) | (c16 << 4)));
        cp_async16(stage + 16384u + sw, &g_wgu_bf[(size_t)(n0 + row) * H_DIM + k0 + c16 * 8]);
        cp_async16(stage + 24576u + sw, &g_wgu_bf[(size_t)(I_DIM + n0 + row) * H_DIM + k0 + c16 * 8]);
    }
    CP_COMMIT();
}

__device__ __forceinline__ float silu_mul(float dg, float du, float xs, float sg, float su) {
    float g = dg * xs * sg;
    float u = du * xs * su;
    return (g / (1.0f + expf(-g))) * u;
}

__global__ __launch_bounds__(256, 2) void gemm1_kernel(const float* __restrict__ x_scale,
                                                       const float* __restrict__ s_wgu) {
    extern __shared__ char smem[];
    const uint32_t sb = smem_u32(smem);
    const int tid = threadIdx.x;
    const int lane = tid & 31;
    const int w = tid >> 5;
    const int wm = w & 3;        // 4 warps over M (32 rows each)
    const int wn = w >> 2;       // 2 warps over N (32 cols each)
    const int m0 = blockIdx.x * 128;
    const int n0 = blockIdx.y * 64;

    float cg[2][4][4] = {};
    float cu[2][4][4] = {};

    g1_load(sb,            tid, m0, n0, 0);
    g1_load(sb + G1_STAGE, tid, m0, n0, 1);

    const int K_IT = H_DIM / 64;  // 64
    int buf = 0;
    for (int kk = 0; kk < K_IT; kk++) {
        CP_WAIT1();
        __syncthreads();
        if (kk + 2 < K_IT) {
            int nb = kk + 2 - ((kk + 2) / 3) * 3;
            g1_load(sb + (uint32_t)nb * G1_STAGE, tid, m0, n0, kk + 2);
        } else {
            CP_COMMIT();
        }
        uint32_t stage = sb + (uint32_t)buf * G1_STAGE;
        uint32_t ta = stage, tg = stage + 16384u, tu = stage + 24576u;
#pragma unroll
        for (int ks = 0; ks < 4; ks++) {
            int kcb = ks * 32;
            uint32_t a[2][4], gb[2][4], ub[2][4];
#pragma unroll
            for (int i = 0; i < 2; i++)
                ldsm_x4(lds_addr(ta, lane, wm * 32 + i * 16, kcb), a[i][0], a[i][1], a[i][2], a[i][3]);
#pragma unroll
            for (int j2 = 0; j2 < 2; j2++) {
                ldsm_x4(lds_addr(tg, lane, wn * 32 + j2 * 16, kcb), gb[j2][0], gb[j2][1], gb[j2][2], gb[j2][3]);
                ldsm_x4(lds_addr(tu, lane, wn * 32 + j2 * 16, kcb), ub[j2][0], ub[j2][1], ub[j2][2], ub[j2][3]);
            }
#pragma unroll
            for (int i = 0; i < 2; i++)
#pragma unroll
                for (int j = 0; j < 4; j++) {
                    mma_bf16(cg[i][j], a[i], gb[j >> 1][j & 1], gb[j >> 1][2 + (j & 1)]);
                    mma_bf16(cu[i][j], a[i], ub[j >> 1][j & 1], ub[j >> 1][2 + (j & 1)]);
                }
        }
        buf = (buf == 2) ? 0 : buf + 1;
    }

    // Epilogue
    const int rbase = m0 + wm * 32 + (lane >> 2);
    const int cofs  = 2 * (lane & 3);
    float amax[4] = {0.f, 0.f, 0.f, 0.f};
    float xs[4];
#pragma unroll
    for (int i = 0; i < 2; i++) {
        xs[i * 2 + 0] = x_scale[rbase + i * 16];
        xs[i * 2 + 1] = x_scale[rbase + i * 16 + 8];
    }
#pragma unroll
    for (int i = 0; i < 2; i++) {
#pragma unroll
        for (int j = 0; j < 4; j++) {
            int gcol = n0 + wn * 32 + j * 8 + cofs;
            float sg0 = __ldg(&s_wgu[gcol]),         sg1 = __ldg(&s_wgu[gcol + 1]);
            float su0 = __ldg(&s_wgu[I_DIM + gcol]), su1 = __ldg(&s_wgu[I_DIM + gcol + 1]);
            int r0 = rbase + i * 16, r1 = r0 + 8;
            float y00 = silu_mul(cg[i][j][0], cu[i][j][0], xs[i * 2], sg0, su0);
            float y01 = silu_mul(cg[i][j][1], cu[i][j][1], xs[i * 2], sg1, su1);
            float y10 = silu_mul(cg[i][j][2], cu[i][j][2], xs[i * 2 + 1], sg0, su0);
            float y11 = silu_mul(cg[i][j][3], cu[i][j][3], xs[i * 2 + 1], sg1, su1);
            amax[i * 2]     = fmaxf(amax[i * 2],     fmaxf(fabsf(y00), fabsf(y01)));
            amax[i * 2 + 1] = fmaxf(amax[i * 2 + 1], fmaxf(fabsf(y10), fabsf(y11)));
            *(float2*)(g_y + (size_t)r0 * I_DIM + gcol) = make_float2(y00, y01);
            *(float2*)(g_y + (size_t)r1 * I_DIM + gcol) = make_float2(y10, y11);
        }
    }
#pragma unroll
    for (int k = 0; k < 4; k++) {
        amax[k] = fmaxf(amax[k], __shfl_xor_sync(0xFFFFFFFF, amax[k], 1));
        amax[k] = fmaxf(amax[k], __shfl_xor_sync(0xFFFFFFFF, amax[k], 2));
    }
    if ((lane & 3) == 0) {
#pragma unroll
        for (int k = 0; k < 4; k++) {
            int r = rbase + (k >> 1) * 16 + (k & 1) * 8;
            atomicMax(&g_rowmax[r], __float_as_uint(amax[k]));
        }
    }
}

// =====================  GEMM2: y_q @ w_down^T (N=64 tiles)  ==================
// CTA 128x64, grid (32, 64) = 2048 CTAs -> 6.9 waves (tail ~1%).
// Stage: A[128x128B] @0 (16KB), B[64x128B] @16384 (8KB) = 24KB. 3 buffers.
#define G2_STAGE 24576
#define G2_SMEM  (3 * G2_STAGE)

__device__ __forceinline__ void g2_load(uint32_t stage, int tid, int m0, int n0, int kk) {
    const int k0 = kk << 6;
#pragma unroll
    for (int i = 0; i < 4; i++) {  // A: 128 rows
        int c = tid + (i << 8);
        int row = c >> 3, c16 = c & 7;
        cp_async16(stage + sw128((uint32_t)((row << 7) | (c16 << 4))),
                   &g_yq_bf[(size_t)(m0 + row) * I_DIM + k0 + c16 * 8]);
    }
#pragma unroll
    for (int i = 0; i < 2; i++) {  // B: 64 rows
        int c = tid + (i << 8);
        int row = c >> 3, c16 = c & 7;
        cp_async16(stage + 16384u + sw128((uint32_t)((row << 7) | (c16 << 4))),
                   &g_wd_bf[(size_t)(n0 + row) * I_DIM + k0 + c16 * 8]);
    }
    CP_COMMIT();
}

__global__ __launch_bounds__(256, 2) void gemm2_kernel(float* __restrict__ out,
                                                       const float* __restrict__ s_wd) {
    extern __shared__ char smem[];
    const uint32_t sb = smem_u32(smem);
    const int tid = threadIdx.x;
    const int lane = tid & 31;
    const int w = tid >> 5;
    const int wm = w & 3;    // 4 warps over M (32 rows each)
    const int wn = w >> 2;   // 2 warps over N (32 cols each)
    const int m0 = blockIdx.x * 128;
    const int n0 = blockIdx.y * 64;

    float acc[2][4][4] = {};

    g2_load(sb,            tid, m0, n0, 0);
    g2_load(sb + G2_STAGE, tid, m0, n0, 1);

    const int K_IT = I_DIM / 64;  // 172
    int buf = 0;
    for (int kk = 0; kk < K_IT; kk++) {
        CP_WAIT1();
        __syncthreads();
        if (kk + 2 < K_IT) {
            int nb = kk + 2 - ((kk + 2) / 3) * 3;
            g2_load(sb + (uint32_t)nb * G2_STAGE, tid, m0, n0, kk + 2);
        } else {
            CP_COMMIT();
        }
        uint32_t stage = sb + (uint32_t)buf * G2_STAGE;
        uint32_t ta = stage, tb = stage + 16384u;
#pragma unroll
        for (int ks = 0; ks < 4; ks++) {
            int kcb = ks * 32;
            uint32_t a[2][4], b[2][4];
#pragma unroll
            for (int i = 0; i < 2; i++)
                ldsm_x4(lds_addr(ta, lane, wm * 32 + i * 16, kcb), a[i][0], a[i][1], a[i][2], a[i][3]);
#pragma unroll
            for (int j2 = 0; j2 < 2; j2++)
                ldsm_x4(lds_addr(tb, lane, wn * 32 + j2 * 16, kcb), b[j2][0], b[j2][1], b[j2][2], b[j2][3]);
#pragma unroll
            for (int i = 0; i < 2; i++)
#pragma unroll
                for (int j = 0; j < 4; j++)
                    mma_bf16(acc[i][j], a[i], b[j >> 1][j & 1], b[j >> 1][2 + (j & 1)]);
        }
        buf = (buf == 2) ? 0 : buf + 1;
    }

    const int rbase = m0 + wm * 32 + (lane >> 2);
    const int cofs  = 2 * (lane & 3);
    float s2[4];
#pragma unroll
    for (int i = 0; i < 2; i++) {
        s2[i * 2 + 0] = fmaxf(__uint_as_float(g_rowmax[rbase + i * 16]), 1e-8f) / 127.0f;
        s2[i * 2 + 1] = fmaxf(__uint_as_float(g_rowmax[rbase + i * 16 + 8]), 1e-8f) / 127.0f;
    }
#pragma unroll
    for (int i = 0; i < 2; i++) {
#pragma unroll
        for (int j = 0; j < 4; j++) {
            int col = n0 + wn * 32 + j * 8 + cofs;
            float sw0 = __ldg(&s_wd[col]), sw1 = __ldg(&s_wd[col + 1]);
            int r0 = rbase + i * 16, r1 = r0 + 8;
            *(float2*)(out + (size_t)r0 * H_DIM + col) =
                make_float2(acc[i][j][0] * s2[i * 2] * sw0,
                            acc[i][j][1] * s2[i * 2] * sw1);
            *(float2*)(out + (size_t)r1 * H_DIM + col) =
                make_float2(acc[i][j][2] * s2[i * 2 + 1] * sw0,
                            acc[i][j][3] * s2[i * 2 + 1] * sw1);
        }
    }
}

// ---------------- launch ----------------------------------------------------
extern "C" void kernel_launch(void* const* d_in, const int* in_sizes, int n_in,
                              void* d_out, int out_size) {
    const int*   x_q     = (const int*)d_in[0];
    const float* x_scale = (const float*)d_in[1];
    const int*   w_gu    = (const int*)d_in[2];
    const float* s_wgu   = (const float*)d_in[3];
    const int*   w_d     = (const int*)d_in[4];
    const float* s_wd    = (const float*)d_in[5];
    float* out = (float*)d_out;

    cudaFuncSetAttribute(gemm1_kernel, cudaFuncAttributeMaxDynamicSharedMemorySize, G1_SMEM);
    cudaFuncSetAttribute(gemm2_kernel, cudaFuncAttributeMaxDynamicSharedMemorySize, G2_SMEM);

    init_kernel<<<2048, 256>>>(x_q, w_gu, w_d);

    dim3 g1(T_DIM / 128, I_DIM / 64);        // (32, 172)
    gemm1_kernel<<<g1, 256, G1_SMEM>>>(x_scale, s_wgu);

    quantize_kernel<<<T_DIM, 256>>>();

    dim3 g2(T_DIM / 128, H_DIM / 64);        // (32, 64) -> 6.9 waves
    gemm2_kernel<<<g2, 256, G2_SMEM>>>(out, s_wd);
}

// round 15
// speedup vs baseline: 1.0344x; 1.0344x over previous
#include <cuda_runtime.h>
#include <cuda_bf16.h>
#include <cstdint>
#include <math.h>

// Problem dims
#define T_DIM 4096
#define H_DIM 4096
#define I_DIM 11008

// ---------------- device scratch (static globals: allocation-free) ----------
__device__ __nv_bfloat16 g_x_bf[(size_t)T_DIM * H_DIM];        // 33.6 MB
__device__ __nv_bfloat16 g_wgu_bf[(size_t)2 * I_DIM * H_DIM];  // 180.4 MB
__device__ __nv_bfloat16 g_wd_bf[(size_t)H_DIM * I_DIM];       // 90.2 MB
__device__ float         g_y[(size_t)T_DIM * I_DIM];           // 180.4 MB
__device__ __nv_bfloat16 g_yq_bf[(size_t)T_DIM * I_DIM];       // 90.2 MB
__device__ unsigned      g_rowmax[T_DIM];

// ---------------- helpers ----------------------------------------------------
__device__ __forceinline__ uint32_t smem_u32(const void* p) {
    uint32_t a;
    asm("{ .reg .u64 t; cvta.to.shared.u64 t, %1; cvt.u32.u64 %0, t; }" : "=r"(a) : "l"(p));
    return a;
}

__device__ __forceinline__ uint32_t sw128(uint32_t off) {
    return off ^ ((off >> 3) & 0x70);
}

__device__ __forceinline__ void cp_async16(uint32_t dst, const void* src) {
    asm volatile("cp.async.cg.shared.global [%0], [%1], 16;" :: "r"(dst), "l"(src));
}
#define CP_COMMIT() asm volatile("cp.async.commit_group;" ::: "memory")
#define CP_WAIT1()  asm volatile("cp.async.wait_group 1;" ::: "memory")

__device__ __forceinline__ void ldsm_x4(uint32_t addr, uint32_t& r0, uint32_t& r1,
                                        uint32_t& r2, uint32_t& r3) {
    asm volatile("ldmatrix.sync.aligned.m8n8.x4.shared.b16 {%0,%1,%2,%3}, [%4];"
                 : "=r"(r0), "=r"(r1), "=r"(r2), "=r"(r3) : "r"(addr));
}

// bf16 HMMA: D(f32) += A(bf16) * B(bf16)
__device__ __forceinline__ void mma_bf16(float* c, const uint32_t* a, uint32_t b0, uint32_t b1) {
    asm volatile(
        "mma.sync.aligned.m16n8k16.row.col.f32.bf16.bf16.f32 "
        "{%0,%1,%2,%3}, {%4,%5,%6,%7}, {%8,%9}, {%0,%1,%2,%3};"
        : "+f"(c[0]), "+f"(c[1]), "+f"(c[2]), "+f"(c[3])
        : "r"(a[0]), "r"(a[1]), "r"(a[2]), "r"(a[3]), "r"(b0), "r"(b1));
}

// ldmatrix lane address inside a [rows x 128B] SW128 tile. kcb = k offset in BYTES.
__device__ __forceinline__ uint32_t lds_addr(uint32_t tile_base, int lane, int mb, int kcb) {
    int row = mb + (lane & 7) + ((lane >> 3) & 1) * 8;
    int kb  = kcb + ((lane >> 4) & 1) * 16;
    return tile_base + sw128((uint32_t)(row * 128 + kb));
}

// ---------------- fused init: converts + rowmax zero --------------------------
__device__ __forceinline__ void conv_seg(const int* __restrict__ src,
                                         __nv_bfloat16* __restrict__ dst,
                                         int n4, int idx, int stride) {
    const int4* s4 = (const int4*)src;
    ushort4* d4 = (ushort4*)dst;
    for (int i = idx; i < n4; i += stride) {
        int4 v = s4[i];
        ushort4 o;
        o.x = __bfloat16_as_ushort(__float2bfloat16_rn((float)v.x));
        o.y = __bfloat16_as_ushort(__float2bfloat16_rn((float)v.y));
        o.z = __bfloat16_as_ushort(__float2bfloat16_rn((float)v.z));
        o.w = __bfloat16_as_ushort(__float2bfloat16_rn((float)v.w));
        d4[i] = o;
    }
}

__global__ __launch_bounds__(256) void init_kernel(const int* __restrict__ x_q,
                                                   const int* __restrict__ w_gu,
                                                   const int* __restrict__ w_d) {
    int idx = blockIdx.x * blockDim.x + threadIdx.x;
    int stride = gridDim.x * blockDim.x;
    conv_seg(x_q,  g_x_bf,   (int)((size_t)T_DIM * H_DIM / 4),     idx, stride);
    conv_seg(w_gu, g_wgu_bf, (int)((size_t)2 * I_DIM * H_DIM / 4), idx, stride);
    conv_seg(w_d,  g_wd_bf,  (int)((size_t)H_DIM * I_DIM / 4),     idx, stride);
    for (int i = idx; i < T_DIM; i += stride) g_rowmax[i] = 0u;
}

__global__ __launch_bounds__(256) void quantize_kernel() {
    int t = blockIdx.x;
    float s2 = fmaxf(__uint_as_float(g_rowmax[t]), 1e-8f) / 127.0f;
    float inv = __frcp_rn(s2);
    const float4* y4 = (const float4*)(g_y + (size_t)t * I_DIM);
    ushort4* q4 = (ushort4*)(g_yq_bf + (size_t)t * I_DIM);
    for (int i = threadIdx.x; i < I_DIM / 4; i += 256) {
        float4 v = y4[i];
        ushort4 o;
        o.x = __bfloat16_as_ushort(__float2bfloat16_rn(fminf(fmaxf(rintf(v.x * inv), -128.f), 127.f)));
        o.y = __bfloat16_as_ushort(__float2bfloat16_rn(fminf(fmaxf(rintf(v.y * inv), -128.f), 127.f)));
        o.z = __bfloat16_as_ushort(__float2bfloat16_rn(fminf(fmaxf(rintf(v.z * inv), -128.f), 127.f)));
        o.w = __bfloat16_as_ushort(__float2bfloat16_rn(fminf(fmaxf(rintf(v.w * inv), -128.f), 127.f)));
        q4[i] = o;
    }
}

// =====================  GEMM1: x @ wgu^T, fused SiLU*up  =====================
// CTA: 128 rows x (64 gate + 64 up cols). 3 buffers, loads 2 stages ahead,
// ONE sync per iteration (load target buf == buf freed by previous iteration).
#define G1_STAGE 32768
#define G1_SMEM  (3 * G1_STAGE)

__device__ __forceinline__ void g1_load(uint32_t stage, int tid, int m0, int n0, int kk) {
    const int k0 = kk << 6;
#pragma unroll
    for (int i = 0; i < 4; i++) {  // A: 128 rows
        int c = tid + (i << 8);
        int row = c >> 3, c16 = c & 7;
        cp_async16(stage + sw128((uint32_t)((row << 7) | (c16 << 4))),
                   &g_x_bf[(size_t)(m0 + row) * H_DIM + k0 + c16 * 8]);
    }
#pragma unroll
    for (int i = 0; i < 2; i++) {  // Bg + Bu: 64 rows each
        int c = tid + (i << 8);
        int row = c >> 3, c16 = c & 7;
        uint32_t sw = sw128((uint32_t)((row << 7) | (c16 << 4)));
        cp_async16(stage + 16384u + sw, &g_wgu_bf[(size_t)(n0 + row) * H_DIM + k0 + c16 * 8]);
        cp_async16(stage + 24576u + sw, &g_wgu_bf[(size_t)(I_DIM + n0 + row) * H_DIM + k0 + c16 * 8]);
    }
    CP_COMMIT();
}

__device__ __forceinline__ float silu_mul(float dg, float du, float xs, float sg, float su) {
    float g = dg * xs * sg;
    float u = du * xs * su;
    return (g / (1.0f + expf(-g))) * u;
}

__global__ __launch_bounds__(256, 2) void gemm1_kernel(const float* __restrict__ x_scale,
                                                       const float* __restrict__ s_wgu) {
    extern __shared__ char smem[];
    const uint32_t sb = smem_u32(smem);
    const int tid = threadIdx.x;
    const int lane = tid & 31;
    const int w = tid >> 5;
    const int wm = w & 3;        // 4 warps over M (32 rows each)
    const int wn = w >> 2;       // 2 warps over N (32 cols each)
    const int m0 = blockIdx.x * 128;
    const int n0 = blockIdx.y * 64;

    float cg[2][4][4] = {};
    float cu[2][4][4] = {};

    g1_load(sb,            tid, m0, n0, 0);
    g1_load(sb + G1_STAGE, tid, m0, n0, 1);

    const int K_IT = H_DIM / 64;  // 64
    int buf = 0;
    for (int kk = 0; kk < K_IT; kk++) {
        CP_WAIT1();
        __syncthreads();
        if (kk + 2 < K_IT) {
            int nb = kk + 2 - ((kk + 2) / 3) * 3;  // (kk+2)%3
            g1_load(sb + (uint32_t)nb * G1_STAGE, tid, m0, n0, kk + 2);
        } else {
            CP_COMMIT();
        }
        uint32_t stage = sb + (uint32_t)buf * G1_STAGE;
        uint32_t ta = stage, tg = stage + 16384u, tu = stage + 24576u;
#pragma unroll
        for (int ks = 0; ks < 4; ks++) {
            int kcb = ks * 32;
            uint32_t a[2][4], gb[2][4], ub[2][4];
#pragma unroll
            for (int i = 0; i < 2; i++)
                ldsm_x4(lds_addr(ta, lane, wm * 32 + i * 16, kcb), a[i][0], a[i][1], a[i][2], a[i][3]);
#pragma unroll
            for (int j2 = 0; j2 < 2; j2++) {
                ldsm_x4(lds_addr(tg, lane, wn * 32 + j2 * 16, kcb), gb[j2][0], gb[j2][1], gb[j2][2], gb[j2][3]);
                ldsm_x4(lds_addr(tu, lane, wn * 32 + j2 * 16, kcb), ub[j2][0], ub[j2][1], ub[j2][2], ub[j2][3]);
            }
#pragma unroll
            for (int i = 0; i < 2; i++)
#pragma unroll
                for (int j = 0; j < 4; j++) {
                    mma_bf16(cg[i][j], a[i], gb[j >> 1][j & 1], gb[j >> 1][2 + (j & 1)]);
                    mma_bf16(cu[i][j], a[i], ub[j >> 1][j & 1], ub[j >> 1][2 + (j & 1)]);
                }
        }
        buf = (buf == 2) ? 0 : buf + 1;
    }

    // Epilogue
    const int rbase = m0 + wm * 32 + (lane >> 2);
    const int cofs  = 2 * (lane & 3);
    float amax[4] = {0.f, 0.f, 0.f, 0.f};
    float xs[4];
#pragma unroll
    for (int i = 0; i < 2; i++) {
        xs[i * 2 + 0] = x_scale[rbase + i * 16];
        xs[i * 2 + 1] = x_scale[rbase + i * 16 + 8];
    }
#pragma unroll
    for (int i = 0; i < 2; i++) {
#pragma unroll
        for (int j = 0; j < 4; j++) {
            int gcol = n0 + wn * 32 + j * 8 + cofs;
            float sg0 = __ldg(&s_wgu[gcol]),         sg1 = __ldg(&s_wgu[gcol + 1]);
            float su0 = __ldg(&s_wgu[I_DIM + gcol]), su1 = __ldg(&s_wgu[I_DIM + gcol + 1]);
            int r0 = rbase + i * 16, r1 = r0 + 8;
            float y00 = silu_mul(cg[i][j][0], cu[i][j][0], xs[i * 2], sg0, su0);
            float y01 = silu_mul(cg[i][j][1], cu[i][j][1], xs[i * 2], sg1, su1);
            float y10 = silu_mul(cg[i][j][2], cu[i][j][2], xs[i * 2 + 1], sg0, su0);
            float y11 = silu_mul(cg[i][j][3], cu[i][j][3], xs[i * 2 + 1], sg1, su1);
            amax[i * 2]     = fmaxf(amax[i * 2],     fmaxf(fabsf(y00), fabsf(y01)));
            amax[i * 2 + 1] = fmaxf(amax[i * 2 + 1], fmaxf(fabsf(y10), fabsf(y11)));
            *(float2*)(g_y + (size_t)r0 * I_DIM + gcol) = make_float2(y00, y01);
            *(float2*)(g_y + (size_t)r1 * I_DIM + gcol) = make_float2(y10, y11);
        }
    }
#pragma unroll
    for (int k = 0; k < 4; k++) {
        amax[k] = fmaxf(amax[k], __shfl_xor_sync(0xFFFFFFFF, amax[k], 1));
        amax[k] = fmaxf(amax[k], __shfl_xor_sync(0xFFFFFFFF, amax[k], 2));
    }
    if ((lane & 3) == 0) {
#pragma unroll
        for (int k = 0; k < 4; k++) {
            int r = rbase + (k >> 1) * 16 + (k & 1) * 8;
            atomicMax(&g_rowmax[r], __float_as_uint(amax[k]));
        }
    }
}

// =====================  GEMM2: y_q @ w_down^T  ===============================
// CTA 128x128. 3 buffers, loads 2 ahead, one sync per iteration.
#define G2_STAGE 32768
#define G2_SMEM  (3 * G2_STAGE)

__device__ __forceinline__ void g2_load(uint32_t stage, int tid, int m0, int n0, int kk) {
    const int k0 = kk << 6;
#pragma unroll
    for (int i = 0; i < 4; i++) {
        int c = tid + (i << 8);
        int row = c >> 3, c16 = c & 7;
        uint32_t sw = sw128((uint32_t)((row << 7) | (c16 << 4)));
        cp_async16(stage + sw,          &g_yq_bf[(size_t)(m0 + row) * I_DIM + k0 + c16 * 8]);
        cp_async16(stage + 16384u + sw, &g_wd_bf[(size_t)(n0 + row) * I_DIM + k0 + c16 * 8]);
    }
    CP_COMMIT();
}

__global__ __launch_bounds__(256, 2) void gemm2_kernel(float* __restrict__ out,
                                                       const float* __restrict__ s_wd) {
    extern __shared__ char smem[];
    const uint32_t sb = smem_u32(smem);
    const int tid = threadIdx.x;
    const int lane = tid & 31;
    const int w = tid >> 5;
    const int wm = w & 3;    // 4 warps over M
    const int wn = w >> 2;   // 2 warps over N (64 cols each)
    const int m0 = blockIdx.x * 128;
    const int n0 = blockIdx.y * 128;

    float acc[2][8][4] = {};

    g2_load(sb,            tid, m0, n0, 0);
    g2_load(sb + G2_STAGE, tid, m0, n0, 1);

    const int K_IT = I_DIM / 64;  // 172
    int buf = 0;
    for (int kk = 0; kk < K_IT; kk++) {
        CP_WAIT1();
        __syncthreads();
        if (kk + 2 < K_IT) {
            int nb = kk + 2 - ((kk + 2) / 3) * 3;  // (kk+2)%3
            g2_load(sb + (uint32_t)nb * G2_STAGE, tid, m0, n0, kk + 2);
        } else {
            CP_COMMIT();
        }
        uint32_t stage = sb + (uint32_t)buf * G2_STAGE;
        uint32_t ta = stage, tb = stage + 16384u;
#pragma unroll
        for (int ks = 0; ks < 4; ks++) {
            int kcb = ks * 32;
            uint32_t a[2][4], b[4][4];
#pragma unroll
            for (int i = 0; i < 2; i++)
                ldsm_x4(lds_addr(ta, lane, wm * 32 + i * 16, kcb), a[i][0], a[i][1], a[i][2], a[i][3]);
#pragma unroll
            for (int j2 = 0; j2 < 4; j2++)
                ldsm_x4(lds_addr(tb, lane, wn * 64 + j2 * 16, kcb), b[j2][0], b[j2][1], b[j2][2], b[j2][3]);
#pragma unroll
            for (int i = 0; i < 2; i++)
#pragma unroll
                for (int j = 0; j < 8; j++)
                    mma_bf16(acc[i][j], a[i], b[j >> 1][j & 1], b[j >> 1][2 + (j & 1)]);
        }
        buf = (buf == 2) ? 0 : buf + 1;
    }

    const int rbase = m0 + wm * 32 + (lane >> 2);
    const int cofs  = 2 * (lane & 3);
    float s2[4];
#pragma unroll
    for (int i = 0; i < 2; i++) {
        s2[i * 2 + 0] = fmaxf(__uint_as_float(g_rowmax[rbase + i * 16]), 1e-8f) / 127.0f;
        s2[i * 2 + 1] = fmaxf(__uint_as_float(g_rowmax[rbase + i * 16 + 8]), 1e-8f) / 127.0f;
    }
#pragma unroll
    for (int i = 0; i < 2; i++) {
#pragma unroll
        for (int j = 0; j < 8; j++) {
            int col = n0 + wn * 64 + j * 8 + cofs;
            float sw0 = __ldg(&s_wd[col]), sw1 = __ldg(&s_wd[col + 1]);
            int r0 = rbase + i * 16, r1 = r0 + 8;
            *(float2*)(out + (size_t)r0 * H_DIM + col) =
                make_float2(acc[i][j][0] * s2[i * 2] * sw0,
                            acc[i][j][1] * s2[i * 2] * sw1);
            *(float2*)(out + (size_t)r1 * H_DIM + col) =
                make_float2(acc[i][j][2] * s2[i * 2 + 1] * sw0,
                            acc[i][j][3] * s2[i * 2 + 1] * sw1);
        }
    }
}

// ---------------- launch ----------------------------------------------------
extern "C" void kernel_launch(void* const* d_in, const int* in_sizes, int n_in,
                              void* d_out, int out_size) {
    const int*   x_q     = (const int*)d_in[0];
    const float* x_scale = (const float*)d_in[1];
    const int*   w_gu    = (const int*)d_in[2];
    const float* s_wgu   = (const float*)d_in[3];
    const int*   w_d     = (const int*)d_in[4];
    const float* s_wd    = (const float*)d_in[5];
    float* out = (float*)d_out;

    cudaFuncSetAttribute(gemm1_kernel, cudaFuncAttributeMaxDynamicSharedMemorySize, G1_SMEM);
    cudaFuncSetAttribute(gemm2_kernel, cudaFuncAttributeMaxDynamicSharedMemorySize, G2_SMEM);

    init_kernel<<<2048, 256>>>(x_q, w_gu, w_d);

    dim3 g1(T_DIM / 128, I_DIM / 64);        // (32, 172)
    gemm1_kernel<<<g1, 256, G1_SMEM>>>(x_scale, s_wgu);

    quantize_kernel<<<T_DIM, 256>>>();

    dim3 g2(T_DIM / 128, H_DIM / 128);       // (32, 32)
    gemm2_kernel<<<g2, 256, G2_SMEM>>>(out, s_wd);
}